// round 1
// baseline (speedup 1.0000x reference)
#include <cuda_runtime.h>
#include <math.h>

#define B_SZ 32768
#define K_SZ 64
#define D_SZ 64
#define ROWS_PER_BLK 64
#define NBLK (B_SZ / ROWS_PER_BLK)   // 512

// EqualizedLR scale factors (GAIN = 1.0)
#define S_MEAN  (1.0f / 64.0f)     // 1/sqrt(K*D)   = 1/sqrt(4096)
#define S_SCALE (1.0f / 512.0f)    // 1/sqrt(K*D*D) = 1/sqrt(262144)
#define S_W     (0.125f)           // 1/sqrt(K)     = 1/8
#define LOG_2PI 1.8378770664093453f

// Scratch (no allocations allowed in kernel_launch)
__device__ float g_W[K_SZ * D_SZ * D_SZ];   // Linv, row-major per k
__device__ float g_m2[K_SZ * D_SZ];         // Linv @ mu per k
__device__ float g_c[K_SZ];                 // -0.5*D*log2pi - halflogdet + logw
__device__ float g_logw[K_SZ];
__device__ float g_partial[NBLK];

// ---------------------------------------------------------------------------
// Kernel A: log-softmax of weights_raw * S_W  (K=64, one block)
// ---------------------------------------------------------------------------
__global__ void logw_kernel(const float* __restrict__ wraw) {
    __shared__ float red[K_SZ];
    int t = threadIdx.x;
    float v = wraw[t] * S_W;
    red[t] = v;
    __syncthreads();
    for (int s = 32; s > 0; s >>= 1) {
        if (t < s) red[t] = fmaxf(red[t], red[t + s]);
        __syncthreads();
    }
    float m = red[0];
    __syncthreads();
    red[t] = __expf(v - m);
    __syncthreads();
    for (int s = 32; s > 0; s >>= 1) {
        if (t < s) red[t] += red[t + s];
        __syncthreads();
    }
    float lse = m + __logf(red[0]);
    g_logw[t] = v - lse;
}

// ---------------------------------------------------------------------------
// Kernel B: per-component preprocessing. grid = K, block = D threads.
//  - build L = tril(pre,-1) + diag(exp(diag(pre))),  pre = scale_raw*S_SCALE
//  - Linv via forward substitution (thread = column)
//  - m2 = Linv @ mu,  c[k] = -0.5*D*log2pi - halflogdet + logw
// ---------------------------------------------------------------------------
__global__ void prep_kernel(const float* __restrict__ means_raw,
                            const float* __restrict__ scale_raw) {
    __shared__ float sL [D_SZ * D_SZ];
    __shared__ float sLI[D_SZ * D_SZ];
    __shared__ float red[D_SZ];
    int k = blockIdx.x;
    int t = threadIdx.x;
    const float* src = scale_raw + (size_t)k * D_SZ * D_SZ;

    for (int idx = t; idx < D_SZ * D_SZ; idx += D_SZ) {
        int i = idx >> 6, j = idx & 63;
        float v = src[idx] * S_SCALE;
        sL[idx] = (j < i) ? v : ((j == i) ? expf(v) : 0.0f);
    }
    // half_log_det = sum(log(exp(diag(pre)))) = sum(diag(pre))
    red[t] = src[t * D_SZ + t] * S_SCALE;
    __syncthreads();
    for (int s = 32; s > 0; s >>= 1) {
        if (t < s) red[t] += red[t + s];
        __syncthreads();
    }
    float hld = red[0];

    // Column t of Linv: solve L y = e_t (forward substitution).
    // Thread t only reads/writes its own column -> no cross-thread races
    // after the syncthreads above. Banks: (m*64 + t) % 32 = t % 32 -> each
    // lane owns one bank, conflict-free.
    int j = t;
    for (int i = 0; i < j; ++i) sLI[i * D_SZ + j] = 0.0f;
    sLI[j * D_SZ + j] = 1.0f / sL[j * D_SZ + j];
    for (int i = j + 1; i < D_SZ; ++i) {
        float s = 0.0f;
        for (int m = j; m < i; ++m)
            s += sL[i * D_SZ + m] * sLI[m * D_SZ + j];
        sLI[i * D_SZ + j] = -s / sL[i * D_SZ + i];
    }
    __syncthreads();

    // m2[i] = sum_j Linv[i][j] * mu[j] (thread = row; only j<=i nonzero)
    float mm = 0.0f;
    for (int jj = 0; jj <= t; ++jj)
        mm += sLI[t * D_SZ + jj] * (means_raw[k * D_SZ + jj] * S_MEAN);
    g_m2[k * D_SZ + t] = mm;

    if (t == 0)
        g_c[k] = -0.5f * (float)D_SZ * LOG_2PI - hld + g_logw[k];

    for (int idx = t; idx < D_SZ * D_SZ; idx += D_SZ)
        g_W[(size_t)k * D_SZ * D_SZ + idx] = sLI[idx];
}

// ---------------------------------------------------------------------------
// Main kernel: thread = one sample b. x row in 64 registers, Linv[k] staged
// in smem (broadcast reads). 4 independent FMA chains per dot product.
// Online logsumexp over k, then deterministic block tree reduction.
// ---------------------------------------------------------------------------
__global__ void __launch_bounds__(ROWS_PER_BLK)
main_kernel(const float* __restrict__ x) {
    __shared__ float sW[D_SZ * D_SZ];   // 16 KB: Linv[k]
    __shared__ float sm2[D_SZ];
    __shared__ float sc;
    __shared__ float red[ROWS_PER_BLK];

    int t = threadIdx.x;
    int b = blockIdx.x * ROWS_PER_BLK + t;

    float xr[D_SZ];
    const float4* xp = (const float4*)(x + (size_t)b * D_SZ);
#pragma unroll
    for (int j4 = 0; j4 < 16; ++j4) {
        float4 v = xp[j4];
        xr[4 * j4 + 0] = v.x; xr[4 * j4 + 1] = v.y;
        xr[4 * j4 + 2] = v.z; xr[4 * j4 + 3] = v.w;
    }

    float mmax = -INFINITY, ssum = 0.0f;

    for (int k = 0; k < K_SZ; ++k) {
        __syncthreads();   // protect sW from previous iteration's readers
        const float4* wsrc = (const float4*)(g_W + (size_t)k * D_SZ * D_SZ);
        float4* wdst = (float4*)sW;
#pragma unroll
        for (int n = 0; n < 16; ++n)
            wdst[t + n * ROWS_PER_BLK] = wsrc[t + n * ROWS_PER_BLK];
        sm2[t] = g_m2[k * D_SZ + t];
        if (t == 0) sc = g_c[k];
        __syncthreads();

        float maha = 0.0f;
#pragma unroll 2
        for (int i = 0; i < D_SZ; ++i) {
            const float4* Lr = (const float4*)(sW + i * D_SZ);
            float z0 = 0.f, z1 = 0.f, z2 = 0.f, z3 = 0.f;
#pragma unroll
            for (int j4 = 0; j4 < 16; j4 += 4) {
                float4 a = Lr[j4 + 0];
                float4 bb = Lr[j4 + 1];
                float4 c4 = Lr[j4 + 2];
                float4 d4 = Lr[j4 + 3];
                z0 = fmaf(a.x,  xr[4*j4 + 0],  fmaf(a.y,  xr[4*j4 + 1],
                     fmaf(a.z,  xr[4*j4 + 2],  fmaf(a.w,  xr[4*j4 + 3],  z0))));
                z1 = fmaf(bb.x, xr[4*j4 + 4],  fmaf(bb.y, xr[4*j4 + 5],
                     fmaf(bb.z, xr[4*j4 + 6],  fmaf(bb.w, xr[4*j4 + 7],  z1))));
                z2 = fmaf(c4.x, xr[4*j4 + 8],  fmaf(c4.y, xr[4*j4 + 9],
                     fmaf(c4.z, xr[4*j4 + 10], fmaf(c4.w, xr[4*j4 + 11], z2))));
                z3 = fmaf(d4.x, xr[4*j4 + 12], fmaf(d4.y, xr[4*j4 + 13],
                     fmaf(d4.z, xr[4*j4 + 14], fmaf(d4.w, xr[4*j4 + 15], z3))));
            }
            float z = ((z0 + z1) + (z2 + z3)) - sm2[i];
            maha = fmaf(z, z, maha);
        }

        float comp = fmaf(-0.5f, maha, sc);
        // branch-free online logsumexp update
        float nm = fmaxf(mmax, comp);
        ssum = ssum * __expf(mmax - nm) + __expf(comp - nm);
        mmax = nm;
    }

    float lp = mmax + __logf(ssum);

    __syncthreads();
    red[t] = lp;
    __syncthreads();
    for (int s = ROWS_PER_BLK / 2; s > 0; s >>= 1) {
        if (t < s) red[t] += red[t + s];
        __syncthreads();
    }
    if (t == 0) g_partial[blockIdx.x] = red[0];
}

// ---------------------------------------------------------------------------
// Final: deterministic tree reduce of block partials -> -mean
// ---------------------------------------------------------------------------
__global__ void final_kernel(float* __restrict__ out) {
    __shared__ float red[NBLK];
    int t = threadIdx.x;
    red[t] = g_partial[t];
    __syncthreads();
    for (int s = NBLK / 2; s > 0; s >>= 1) {
        if (t < s) red[t] += red[t + s];
        __syncthreads();
    }
    if (t == 0) out[0] = -red[0] / (float)B_SZ;
}

// ---------------------------------------------------------------------------
extern "C" void kernel_launch(void* const* d_in, const int* in_sizes, int n_in,
                              void* d_out, int out_size) {
    // Defensive identification by element count (metadata order: x, means,
    // scale, weights — sizes 2097152 / 4096 / 262144 / 64, all distinct).
    const float* x = nullptr;
    const float* means_raw = nullptr;
    const float* scale_raw = nullptr;
    const float* weights_raw = nullptr;
    for (int i = 0; i < n_in; ++i) {
        switch (in_sizes[i]) {
            case B_SZ * D_SZ:        x = (const float*)d_in[i]; break;
            case K_SZ * D_SZ:        means_raw = (const float*)d_in[i]; break;
            case K_SZ * D_SZ * D_SZ: scale_raw = (const float*)d_in[i]; break;
            case K_SZ:               weights_raw = (const float*)d_in[i]; break;
        }
    }

    logw_kernel<<<1, K_SZ>>>(weights_raw);
    prep_kernel<<<K_SZ, D_SZ>>>(means_raw, scale_raw);
    main_kernel<<<NBLK, ROWS_PER_BLK>>>(x);
    final_kernel<<<1, NBLK>>>((float*)d_out);
}

// round 2
// speedup vs baseline: 1.0175x; 1.0175x over previous
#include <cuda_runtime.h>
#include <math.h>

#define B_SZ 32768
#define K_SZ 64
#define D_SZ 64
#define ROWS_PER_BLK 64
#define NBLK (B_SZ / ROWS_PER_BLK)   // 512

// EqualizedLR scale factors (GAIN = 1.0)
#define S_MEAN  (1.0f / 64.0f)     // 1/sqrt(K*D)   = 1/sqrt(4096)
#define S_SCALE (1.0f / 512.0f)    // 1/sqrt(K*D*D) = 1/sqrt(262144)
#define S_W     (0.125f)           // 1/sqrt(K)     = 1/8
#define LOG_2PI 1.8378770664093453f

// Scratch (no allocations allowed in kernel_launch)
__device__ float g_W[K_SZ * D_SZ * D_SZ];   // Linv, row-major per k
__device__ float g_m2[K_SZ * D_SZ];         // Linv @ mu per k
__device__ float g_c[K_SZ];                 // -0.5*D*log2pi - halflogdet + logw
__device__ float g_logw[K_SZ];
__device__ float g_partial[NBLK];

// ---- packed fp32x2 ops (Blackwell sm_103a; SASS FFMA2 — ptxas never emits
// these from C++, only via explicit PTX) --------------------------------
typedef unsigned long long u64;

__device__ __forceinline__ void ffma2(u64 &acc, u64 a, u64 b) {
    asm("fma.rn.f32x2 %0, %1, %2, %0;" : "+l"(acc) : "l"(a), "l"(b));
}
__device__ __forceinline__ u64 fadd2(u64 a, u64 b) {
    u64 r;
    asm("add.rn.f32x2 %0, %1, %2;" : "=l"(r) : "l"(a), "l"(b));
    return r;
}
__device__ __forceinline__ float unpack_sum(u64 v) {
    float lo, hi;
    asm("mov.b64 {%0, %1}, %2;" : "=f"(lo), "=f"(hi) : "l"(v));
    return lo + hi;
}

// ---------------------------------------------------------------------------
// Kernel A: log-softmax of weights_raw * S_W  (K=64, one block)
// ---------------------------------------------------------------------------
__global__ void logw_kernel(const float* __restrict__ wraw) {
    __shared__ float red[K_SZ];
    int t = threadIdx.x;
    float v = wraw[t] * S_W;
    red[t] = v;
    __syncthreads();
    for (int s = 32; s > 0; s >>= 1) {
        if (t < s) red[t] = fmaxf(red[t], red[t + s]);
        __syncthreads();
    }
    float m = red[0];
    __syncthreads();
    red[t] = __expf(v - m);
    __syncthreads();
    for (int s = 32; s > 0; s >>= 1) {
        if (t < s) red[t] += red[t + s];
        __syncthreads();
    }
    float lse = m + __logf(red[0]);
    g_logw[t] = v - lse;
}

// ---------------------------------------------------------------------------
// Kernel B: per-component preprocessing. grid = K, block = D threads.
// ---------------------------------------------------------------------------
__global__ void prep_kernel(const float* __restrict__ means_raw,
                            const float* __restrict__ scale_raw) {
    __shared__ float sL [D_SZ * D_SZ];
    __shared__ float sLI[D_SZ * D_SZ];
    __shared__ float red[D_SZ];
    int k = blockIdx.x;
    int t = threadIdx.x;
    const float* src = scale_raw + (size_t)k * D_SZ * D_SZ;

    for (int idx = t; idx < D_SZ * D_SZ; idx += D_SZ) {
        int i = idx >> 6, j = idx & 63;
        float v = src[idx] * S_SCALE;
        sL[idx] = (j < i) ? v : ((j == i) ? expf(v) : 0.0f);
    }
    // half_log_det = sum(log(exp(diag(pre)))) = sum(diag(pre))
    red[t] = src[t * D_SZ + t] * S_SCALE;
    __syncthreads();
    for (int s = 32; s > 0; s >>= 1) {
        if (t < s) red[t] += red[t + s];
        __syncthreads();
    }
    float hld = red[0];

    // Column t of Linv via forward substitution; conflict-free banks.
    int j = t;
    for (int i = 0; i < j; ++i) sLI[i * D_SZ + j] = 0.0f;
    sLI[j * D_SZ + j] = 1.0f / sL[j * D_SZ + j];
    for (int i = j + 1; i < D_SZ; ++i) {
        float s = 0.0f;
        for (int m = j; m < i; ++m)
            s += sL[i * D_SZ + m] * sLI[m * D_SZ + j];
        sLI[i * D_SZ + j] = -s / sL[i * D_SZ + i];
    }
    __syncthreads();

    // m2[i] = sum_j Linv[i][j] * mu[j]
    float mm = 0.0f;
    for (int jj = 0; jj <= t; ++jj)
        mm += sLI[t * D_SZ + jj] * (means_raw[k * D_SZ + jj] * S_MEAN);
    g_m2[k * D_SZ + t] = mm;

    if (t == 0)
        g_c[k] = -0.5f * (float)D_SZ * LOG_2PI - hld + g_logw[k];

    for (int idx = t; idx < D_SZ * D_SZ; idx += D_SZ)
        g_W[(size_t)k * D_SZ * D_SZ + idx] = sLI[idx];
}

// ---------------------------------------------------------------------------
// Main kernel: thread = one sample. x in 32 packed f32x2 registers, Linv[k]
// staged in smem, dot products via FFMA2 (2 FMAs / instruction).
// ---------------------------------------------------------------------------
__global__ void __launch_bounds__(ROWS_PER_BLK)
main_kernel(const float* __restrict__ x) {
    __shared__ float sW[D_SZ * D_SZ];   // 16 KB: Linv[k]
    __shared__ float sm2[D_SZ];
    __shared__ float sc;
    __shared__ float red[ROWS_PER_BLK];

    int t = threadIdx.x;
    int b = blockIdx.x * ROWS_PER_BLK + t;

    // x row as 32 packed f32x2 pairs (adjacent j elements share a pair)
    u64 xr2[D_SZ / 2];
    const ulonglong2* xp = (const ulonglong2*)(x + (size_t)b * D_SZ);
#pragma unroll
    for (int q = 0; q < 16; ++q) {
        ulonglong2 v = xp[q];
        xr2[2 * q + 0] = v.x;
        xr2[2 * q + 1] = v.y;
    }

    float mmax = -INFINITY, ssum = 0.0f;

    for (int k = 0; k < K_SZ; ++k) {
        __syncthreads();   // protect sW from previous iteration's readers
        const float4* wsrc = (const float4*)(g_W + (size_t)k * D_SZ * D_SZ);
        float4* wdst = (float4*)sW;
#pragma unroll
        for (int n = 0; n < 16; ++n)
            wdst[t + n * ROWS_PER_BLK] = wsrc[t + n * ROWS_PER_BLK];
        sm2[t] = g_m2[k * D_SZ + t];
        if (t == 0) sc = g_c[k];
        __syncthreads();

        float maha = 0.0f;
#pragma unroll 2
        for (int i = 0; i < D_SZ; ++i) {
            // W row i: 16 x LDS.128, each = 2 packed f32x2 operands
            const ulonglong2* Lr = (const ulonglong2*)(sW + i * D_SZ);
            u64 z0 = 0ull, z1 = 0ull, z2 = 0ull, z3 = 0ull;
#pragma unroll
            for (int q = 0; q < 16; q += 4) {
                ulonglong2 a  = Lr[q + 0];
                ulonglong2 bq = Lr[q + 1];
                ulonglong2 c  = Lr[q + 2];
                ulonglong2 d  = Lr[q + 3];
                ffma2(z0, a.x,  xr2[2 * q + 0]);
                ffma2(z0, a.y,  xr2[2 * q + 1]);
                ffma2(z1, bq.x, xr2[2 * q + 2]);
                ffma2(z1, bq.y, xr2[2 * q + 3]);
                ffma2(z2, c.x,  xr2[2 * q + 4]);
                ffma2(z2, c.y,  xr2[2 * q + 5]);
                ffma2(z3, d.x,  xr2[2 * q + 6]);
                ffma2(z3, d.y,  xr2[2 * q + 7]);
            }
            u64 zs = fadd2(fadd2(z0, z1), fadd2(z2, z3));
            float z = unpack_sum(zs) - sm2[i];
            maha = fmaf(z, z, maha);
        }

        float comp = fmaf(-0.5f, maha, sc);
        // branch-free online logsumexp update
        float nm = fmaxf(mmax, comp);
        ssum = ssum * __expf(mmax - nm) + __expf(comp - nm);
        mmax = nm;
    }

    float lp = mmax + __logf(ssum);

    __syncthreads();
    red[t] = lp;
    __syncthreads();
    for (int s = ROWS_PER_BLK / 2; s > 0; s >>= 1) {
        if (t < s) red[t] += red[t + s];
        __syncthreads();
    }
    if (t == 0) g_partial[blockIdx.x] = red[0];
}

// ---------------------------------------------------------------------------
// Final: deterministic tree reduce of block partials -> -mean
// ---------------------------------------------------------------------------
__global__ void final_kernel(float* __restrict__ out) {
    __shared__ float red[NBLK];
    int t = threadIdx.x;
    red[t] = g_partial[t];
    __syncthreads();
    for (int s = NBLK / 2; s > 0; s >>= 1) {
        if (t < s) red[t] += red[t + s];
        __syncthreads();
    }
    if (t == 0) out[0] = -red[0] / (float)B_SZ;
}

// ---------------------------------------------------------------------------
extern "C" void kernel_launch(void* const* d_in, const int* in_sizes, int n_in,
                              void* d_out, int out_size) {
    const float* x = nullptr;
    const float* means_raw = nullptr;
    const float* scale_raw = nullptr;
    const float* weights_raw = nullptr;
    for (int i = 0; i < n_in; ++i) {
        switch (in_sizes[i]) {
            case B_SZ * D_SZ:        x = (const float*)d_in[i]; break;
            case K_SZ * D_SZ:        means_raw = (const float*)d_in[i]; break;
            case K_SZ * D_SZ * D_SZ: scale_raw = (const float*)d_in[i]; break;
            case K_SZ:               weights_raw = (const float*)d_in[i]; break;
        }
    }

    logw_kernel<<<1, K_SZ>>>(weights_raw);
    prep_kernel<<<K_SZ, D_SZ>>>(means_raw, scale_raw);
    main_kernel<<<NBLK, ROWS_PER_BLK>>>(x);
    final_kernel<<<1, NBLK>>>((float*)d_out);
}

// round 6
// speedup vs baseline: 3.5944x; 3.5326x over previous
#include <cuda_runtime.h>
#include <cuda_bf16.h>
#include <math.h>

#define B_SZ 32768
#define K_SZ 64
#define D_SZ 64
#define BLK_THREADS 128
#define SAMPLES_PER_BLK 64
#define NBLK 512

#define S_MEAN  (1.0f / 64.0f)
#define S_SCALE (1.0f / 512.0f)
#define S_W     (0.125f)
#define LOG_2PI 1.8378770664093453f
#define NEG_BIG (-3.0e38f)

#define WROW_BYTES 144

__device__ __nv_bfloat16 g_Whi[K_SZ * D_SZ * D_SZ];
__device__ __nv_bfloat16 g_Wlo[K_SZ * D_SZ * D_SZ];
__device__ float g_m2[K_SZ * D_SZ];
__device__ float g_c[K_SZ];
__device__ float g_logw[K_SZ];
__device__ float g_partial[NBLK];

__device__ __forceinline__ void cp16(unsigned dst, const void* src) {
    asm volatile("cp.async.cg.shared.global [%0], [%1], 16;"
                 :: "r"(dst), "l"(__cvta_generic_to_global(src)) : "memory");
}
__device__ __forceinline__ void cp_commit() {
    asm volatile("cp.async.commit_group;" ::: "memory");
}
__device__ __forceinline__ void cp_wait1() {
    asm volatile("cp.async.wait_group 1;" ::: "memory");
}
__device__ __forceinline__ void cp_wait0() {
    asm volatile("cp.async.wait_group 0;" ::: "memory");
}

// register-list braces written as octal escapes to keep this file free of
// literal brace characters inside string constants
__device__ __forceinline__ void ldsm4(unsigned& r0, unsigned& r1,
                                      unsigned& r2, unsigned& r3, unsigned a) {
    asm volatile("ldmatrix.sync.aligned.m8n8.x4.shared.b16 \173%0,%1,%2,%3\175, [%4];"
                 : "=r"(r0), "=r"(r1), "=r"(r2), "=r"(r3) : "r"(a));
}

__device__ __forceinline__ void mma_bf16(float& c0, float& c1, float& c2, float& c3,
                                         unsigned a0, unsigned a1, unsigned a2, unsigned a3,
                                         unsigned b0, unsigned b1) {
    asm volatile("mma.sync.aligned.m16n8k16.row.col.f32.bf16.bf16.f32 "
                 "\173%0,%1,%2,%3\175, \173%4,%5,%6,%7\175, \173%8,%9\175, \173%0,%1,%2,%3\175;"
                 : "+f"(c0), "+f"(c1), "+f"(c2), "+f"(c3)
                 : "r"(a0), "r"(a1), "r"(a2), "r"(a3), "r"(b0), "r"(b1));
}

__device__ __forceinline__ unsigned pack_bf16x2(float lo, float hi) {
    __nv_bfloat162 h = __floats2bfloat162_rn(lo, hi);
    return *reinterpret_cast<unsigned*>(&h);
}

__device__ __forceinline__ void stage_k(int tid, int k,
                                        unsigned wbase_hi, unsigned wbase_lo,
                                        unsigned m2base) {
    for (int c = tid; c < 1040; c += BLK_THREADS) {
        if (c < 512) {
            int row = c >> 3;
            int cc = c & 7;
            cp16(wbase_hi + row * WROW_BYTES + cc * 16,
                 g_Whi + (size_t)k * 4096 + row * 64 + cc * 8);
        } else if (c < 1024) {
            int rem = c - 512;
            int row = rem >> 3;
            int cc = rem & 7;
            cp16(wbase_lo + row * WROW_BYTES + cc * 16,
                 g_Wlo + (size_t)k * 4096 + row * 64 + cc * 8);
        } else {
            int i = c - 1024;
            cp16(m2base + i * 16, g_m2 + k * 64 + i * 4);
        }
    }
}

__global__ void logw_kernel(const float* __restrict__ wraw) {
    __shared__ float red[K_SZ];
    int t = threadIdx.x;
    float v = wraw[t] * S_W;
    red[t] = v;
    __syncthreads();
    for (int s = 32; s > 0; s >>= 1) {
        if (t < s) red[t] = fmaxf(red[t], red[t + s]);
        __syncthreads();
    }
    float m = red[0];
    __syncthreads();
    red[t] = __expf(v - m);
    __syncthreads();
    for (int s = 32; s > 0; s >>= 1) {
        if (t < s) red[t] += red[t + s];
        __syncthreads();
    }
    float lse = m + __logf(red[0]);
    g_logw[t] = v - lse;
}

__global__ void prep_kernel(const float* __restrict__ means_raw,
                            const float* __restrict__ scale_raw) {
    __shared__ float sL [D_SZ * D_SZ];
    __shared__ float sLI[D_SZ * D_SZ];
    __shared__ float red[D_SZ];
    int k = blockIdx.x;
    int t = threadIdx.x;
    const float* src = scale_raw + (size_t)k * D_SZ * D_SZ;

    for (int idx = t; idx < D_SZ * D_SZ; idx += D_SZ) {
        int i = idx >> 6;
        int j = idx & 63;
        float v = src[idx] * S_SCALE;
        float dv = expf(v);
        float off = (j < i) ? v : 0.0f;
        sL[idx] = (j == i) ? dv : off;
    }
    red[t] = src[t * D_SZ + t] * S_SCALE;
    __syncthreads();
    for (int s = 32; s > 0; s >>= 1) {
        if (t < s) red[t] += red[t + s];
        __syncthreads();
    }
    float hld = red[0];

    int j = t;
    for (int i = 0; i < j; ++i) sLI[i * D_SZ + j] = 0.0f;
    sLI[j * D_SZ + j] = 1.0f / sL[j * D_SZ + j];
    for (int i = j + 1; i < D_SZ; ++i) {
        float s = 0.0f;
        for (int m = j; m < i; ++m)
            s += sL[i * D_SZ + m] * sLI[m * D_SZ + j];
        sLI[i * D_SZ + j] = -s / sL[i * D_SZ + i];
    }
    __syncthreads();

    float mm = 0.0f;
    for (int jj = 0; jj <= t; ++jj)
        mm += sLI[t * D_SZ + jj] * (means_raw[k * D_SZ + jj] * S_MEAN);
    g_m2[k * D_SZ + t] = mm;

    if (t == 0)
        g_c[k] = -0.5f * (float)D_SZ * LOG_2PI - hld + g_logw[k];

    for (int idx = t; idx < D_SZ * D_SZ; idx += D_SZ) {
        float v = sLI[idx];
        __nv_bfloat16 h = __float2bfloat16(v);
        g_Whi[(size_t)k * 4096 + idx] = h;
        g_Wlo[(size_t)k * 4096 + idx] = __float2bfloat16(v - __bfloat162float(h));
    }
}

__global__ void __launch_bounds__(BLK_THREADS)
main_kernel(const float* __restrict__ x) {
    __shared__ __align__(16) unsigned char sWhi[2][D_SZ * WROW_BYTES];
    __shared__ __align__(16) unsigned char sWlo[2][D_SZ * WROW_BYTES];
    __shared__ float sm2[2][D_SZ];
    __shared__ float sred[SAMPLES_PER_BLK];

    const int tid  = threadIdx.x;
    const int warp = tid >> 5;
    const int lane = tid & 31;
    const int g    = lane >> 2;
    const int qt   = lane & 3;
    const int mbase = blockIdx.x * SAMPLES_PER_BLK + warp * 16;

    unsigned Ahi[16];
    unsigned Alo[16];
    const float* xr0 = x + (size_t)(mbase + g) * D_SZ;
    const float* xr1 = x + (size_t)(mbase + g + 8) * D_SZ;
#pragma unroll
    for (int jt = 0; jt < 4; ++jt) {
#pragma unroll
        for (int part = 0; part < 4; ++part) {
            const float* rp = (part & 1) ? xr1 : xr0;
            int jj = jt * 16 + 2 * qt + ((part & 2) ? 8 : 0);
            float v0 = rp[jj];
            float v1 = rp[jj + 1];
            float h0 = __bfloat162float(__float2bfloat16(v0));
            float h1 = __bfloat162float(__float2bfloat16(v1));
            Ahi[jt * 4 + part] = pack_bf16x2(h0, h1);
            Alo[jt * 4 + part] = pack_bf16x2(v0 - h0, v1 - h1);
        }
    }

    unsigned whiB0 = (unsigned)__cvta_generic_to_shared(&sWhi[0][0]);
    unsigned whiB1 = (unsigned)__cvta_generic_to_shared(&sWhi[1][0]);
    unsigned wloB0 = (unsigned)__cvta_generic_to_shared(&sWlo[0][0]);
    unsigned wloB1 = (unsigned)__cvta_generic_to_shared(&sWlo[1][0]);
    unsigned m2B0  = (unsigned)__cvta_generic_to_shared(&sm2[0][0]);
    unsigned m2B1  = (unsigned)__cvta_generic_to_shared(&sm2[1][0]);

    float mx0 = NEG_BIG;
    float s0 = 0.0f;
    float mx1 = NEG_BIG;
    float s1 = 0.0f;

    stage_k(tid, 0, whiB0, wloB0, m2B0);
    cp_commit();

    const unsigned rowoff = (lane & 7) * WROW_BYTES + (lane >> 3) * 16;

    for (int k = 0; k < K_SZ; ++k) {
        int buf = k & 1;
        unsigned whiB = buf ? whiB1 : whiB0;
        unsigned wloB = buf ? wloB1 : wloB0;
        if (k + 1 < K_SZ) {
            unsigned nwhi = buf ? whiB0 : whiB1;
            unsigned nwlo = buf ? wloB0 : wloB1;
            unsigned nm2  = buf ? m2B0  : m2B1;
            stage_k(tid, k + 1, nwhi, nwlo, nm2);
            cp_commit();
            cp_wait1();
        } else {
            cp_wait0();
        }
        __syncthreads();

        float ck = g_c[k];
        float mh0 = 0.0f;
        float mh1 = 0.0f;
#pragma unroll
        for (int nt = 0; nt < 8; ++nt) {
            unsigned ntoff = nt * 8 * WROW_BYTES + rowoff;
            unsigned bh0, bh1, bh2, bh3, bg0, bg1, bg2, bg3;
            unsigned bl0, bl1, bl2, bl3, bm0, bm1, bm2, bm3;
            ldsm4(bh0, bh1, bh2, bh3, whiB + ntoff);
            ldsm4(bg0, bg1, bg2, bg3, whiB + ntoff + 64);
            ldsm4(bl0, bl1, bl2, bl3, wloB + ntoff);
            ldsm4(bm0, bm1, bm2, bm3, wloB + ntoff + 64);

            float c0 = 0.0f;
            float c1 = 0.0f;
            float c2 = 0.0f;
            float c3 = 0.0f;
            mma_bf16(c0, c1, c2, c3, Ahi[0],  Ahi[1],  Ahi[2],  Ahi[3],  bh0, bh1);
            mma_bf16(c0, c1, c2, c3, Ahi[0],  Ahi[1],  Ahi[2],  Ahi[3],  bl0, bl1);
            mma_bf16(c0, c1, c2, c3, Alo[0],  Alo[1],  Alo[2],  Alo[3],  bh0, bh1);
            mma_bf16(c0, c1, c2, c3, Ahi[4],  Ahi[5],  Ahi[6],  Ahi[7],  bh2, bh3);
            mma_bf16(c0, c1, c2, c3, Ahi[4],  Ahi[5],  Ahi[6],  Ahi[7],  bl2, bl3);
            mma_bf16(c0, c1, c2, c3, Alo[4],  Alo[5],  Alo[6],  Alo[7],  bh2, bh3);
            mma_bf16(c0, c1, c2, c3, Ahi[8],  Ahi[9],  Ahi[10], Ahi[11], bg0, bg1);
            mma_bf16(c0, c1, c2, c3, Ahi[8],  Ahi[9],  Ahi[10], Ahi[11], bm0, bm1);
            mma_bf16(c0, c1, c2, c3, Alo[8],  Alo[9],  Alo[10], Alo[11], bg0, bg1);
            mma_bf16(c0, c1, c2, c3, Ahi[12], Ahi[13], Ahi[14], Ahi[15], bg2, bg3);
            mma_bf16(c0, c1, c2, c3, Ahi[12], Ahi[13], Ahi[14], Ahi[15], bm2, bm3);
            mma_bf16(c0, c1, c2, c3, Alo[12], Alo[13], Alo[14], Alo[15], bg2, bg3);

            float m2a = sm2[buf][nt * 8 + 2 * qt];
            float m2b = sm2[buf][nt * 8 + 2 * qt + 1];
            float z0 = c0 - m2a;
            float z1 = c1 - m2b;
            float z2 = c2 - m2a;
            float z3 = c3 - m2b;
            mh0 = fmaf(z0, z0, fmaf(z1, z1, mh0));
            mh1 = fmaf(z2, z2, fmaf(z3, z3, mh1));
        }
        mh0 += __shfl_xor_sync(0xffffffffu, mh0, 1);
        mh0 += __shfl_xor_sync(0xffffffffu, mh0, 2);
        mh1 += __shfl_xor_sync(0xffffffffu, mh1, 1);
        mh1 += __shfl_xor_sync(0xffffffffu, mh1, 2);

        float comp0 = fmaf(-0.5f, mh0, ck);
        float comp1 = fmaf(-0.5f, mh1, ck);
        float nm0 = fmaxf(mx0, comp0);
        s0 = s0 * __expf(mx0 - nm0) + __expf(comp0 - nm0);
        mx0 = nm0;
        float nm1 = fmaxf(mx1, comp1);
        s1 = s1 * __expf(mx1 - nm1) + __expf(comp1 - nm1);
        mx1 = nm1;

        __syncthreads();
    }

    float lp0 = mx0 + __logf(s0);
    float lp1 = mx1 + __logf(s1);
    if (qt == 0) {
        sred[warp * 16 + g] = lp0;
        sred[warp * 16 + 8 + g] = lp1;
    }
    __syncthreads();
    for (int s = SAMPLES_PER_BLK / 2; s > 0; s >>= 1) {
        if (tid < s) sred[tid] += sred[tid + s];
        __syncthreads();
    }
    if (tid == 0) g_partial[blockIdx.x] = sred[0];
}

__global__ void final_kernel(float* __restrict__ out) {
    __shared__ float red[NBLK];
    int t = threadIdx.x;
    red[t] = g_partial[t];
    __syncthreads();
    for (int s = NBLK / 2; s > 0; s >>= 1) {
        if (t < s) red[t] += red[t + s];
        __syncthreads();
    }
    if (t == 0) out[0] = -red[0] / (float)B_SZ;
}

extern "C" void kernel_launch(void* const* d_in, const int* in_sizes, int n_in,
                              void* d_out, int out_size) {
    const float* x = 0;
    const float* means_raw = 0;
    const float* scale_raw = 0;
    const float* weights_raw = 0;
    for (int i = 0; i < n_in; ++i) {
        if (in_sizes[i] == B_SZ * D_SZ)        x = (const float*)d_in[i];
        if (in_sizes[i] == K_SZ * D_SZ)        means_raw = (const float*)d_in[i];
        if (in_sizes[i] == K_SZ * D_SZ * D_SZ) scale_raw = (const float*)d_in[i];
        if (in_sizes[i] == K_SZ)               weights_raw = (const float*)d_in[i];
    }

    logw_kernel<<<1, K_SZ>>>(weights_raw);
    prep_kernel<<<K_SZ, D_SZ>>>(means_raw, scale_raw);
    main_kernel<<<NBLK, BLK_THREADS>>>(x);
    final_kernel<<<1, NBLK>>>((float*)d_out);
}

// round 9
// speedup vs baseline: 4.6181x; 1.2848x over previous
#include <cuda_runtime.h>
#include <cuda_bf16.h>
#include <math.h>

#define B_SZ 32768
#define K_SZ 64
#define D_SZ 64
#define BLK_THREADS 128
#define SAMPLES_PER_BLK 128
#define NBLK_MAIN 256

#define S_MEAN  (1.0f / 64.0f)
#define S_SCALE (1.0f / 512.0f)
#define S_W     (0.125f)
#define LOG_2PI 1.8378770664093453f
#define NEG_BIG (-3.0e38f)

#define WROW_BYTES 144

__device__ __nv_bfloat16 g_Whi[K_SZ * D_SZ * D_SZ];
__device__ __nv_bfloat16 g_Wlo[K_SZ * D_SZ * D_SZ];
__device__ float g_m2[K_SZ * D_SZ];
__device__ float g_c[K_SZ];
__device__ float g_logw[K_SZ];
__device__ float g_partial[NBLK_MAIN];

__device__ __forceinline__ void cp16(unsigned dst, const void* src) {
    asm volatile("cp.async.cg.shared.global [%0], [%1], 16;"
                 :: "r"(dst), "l"(__cvta_generic_to_global(src)) : "memory");
}
__device__ __forceinline__ void cp_commit() {
    asm volatile("cp.async.commit_group;" ::: "memory");
}
__device__ __forceinline__ void cp_wait1() {
    asm volatile("cp.async.wait_group 1;" ::: "memory");
}
__device__ __forceinline__ void cp_wait0() {
    asm volatile("cp.async.wait_group 0;" ::: "memory");
}

// register-list braces written as octal escapes: keep this file free of
// literal brace characters inside string constants
__device__ __forceinline__ void ldsm4(unsigned& r0, unsigned& r1,
                                      unsigned& r2, unsigned& r3, unsigned a) {
    asm volatile("ldmatrix.sync.aligned.m8n8.x4.shared.b16 \173%0,%1,%2,%3\175, [%4];"
                 : "=r"(r0), "=r"(r1), "=r"(r2), "=r"(r3) : "r"(a));
}

__device__ __forceinline__ void mma_bf16(float& c0, float& c1, float& c2, float& c3,
                                         unsigned a0, unsigned a1, unsigned a2, unsigned a3,
                                         unsigned b0, unsigned b1) {
    asm volatile("mma.sync.aligned.m16n8k16.row.col.f32.bf16.bf16.f32 "
                 "\173%0,%1,%2,%3\175, \173%4,%5,%6,%7\175, \173%8,%9\175, \173%0,%1,%2,%3\175;"
                 : "+f"(c0), "+f"(c1), "+f"(c2), "+f"(c3)
                 : "r"(a0), "r"(a1), "r"(a2), "r"(a3), "r"(b0), "r"(b1));
}

__device__ __forceinline__ unsigned pack_bf16x2(float lo, float hi) {
    __nv_bfloat162 h = __floats2bfloat162_rn(lo, hi);
    return *reinterpret_cast<unsigned*>(&h);
}

__device__ __forceinline__ void stage_k(int tid, int k,
                                        unsigned wbase_hi, unsigned wbase_lo,
                                        unsigned m2base) {
    for (int c = tid; c < 1040; c += BLK_THREADS) {
        if (c < 512) {
            int row = c >> 3;
            int cc = c & 7;
            cp16(wbase_hi + row * WROW_BYTES + cc * 16,
                 g_Whi + (size_t)k * 4096 + row * 64 + cc * 8);
        } else if (c < 1024) {
            int rem = c - 512;
            int row = rem >> 3;
            int cc = rem & 7;
            cp16(wbase_lo + row * WROW_BYTES + cc * 16,
                 g_Wlo + (size_t)k * 4096 + row * 64 + cc * 8);
        } else {
            int i = c - 1024;
            cp16(m2base + i * 16, g_m2 + k * 64 + i * 4);
        }
    }
}

__global__ void logw_kernel(const float* __restrict__ wraw) {
    __shared__ float red[K_SZ];
    int t = threadIdx.x;
    float v = wraw[t] * S_W;
    red[t] = v;
    __syncthreads();
    for (int s = 32; s > 0; s >>= 1) {
        if (t < s) red[t] = fmaxf(red[t], red[t + s]);
        __syncthreads();
    }
    float m = red[0];
    __syncthreads();
    red[t] = __expf(v - m);
    __syncthreads();
    for (int s = 32; s > 0; s >>= 1) {
        if (t < s) red[t] += red[t + s];
        __syncthreads();
    }
    float lse = m + __logf(red[0]);
    g_logw[t] = v - lse;
}

__global__ void prep_kernel(const float* __restrict__ means_raw,
                            const float* __restrict__ scale_raw) {
    __shared__ float sL [D_SZ * D_SZ];
    __shared__ float sLI[D_SZ * D_SZ];
    __shared__ float red[D_SZ];
    int k = blockIdx.x;
    int t = threadIdx.x;
    const float* src = scale_raw + (size_t)k * D_SZ * D_SZ;

    for (int idx = t; idx < D_SZ * D_SZ; idx += D_SZ) {
        int i = idx >> 6;
        int j = idx & 63;
        float v = src[idx] * S_SCALE;
        float dv = expf(v);
        float off = (j < i) ? v : 0.0f;
        sL[idx] = (j == i) ? dv : off;
    }
    red[t] = src[t * D_SZ + t] * S_SCALE;
    __syncthreads();
    for (int s = 32; s > 0; s >>= 1) {
        if (t < s) red[t] += red[t + s];
        __syncthreads();
    }
    float hld = red[0];

    int j = t;
    for (int i = 0; i < j; ++i) sLI[i * D_SZ + j] = 0.0f;
    sLI[j * D_SZ + j] = 1.0f / sL[j * D_SZ + j];
    for (int i = j + 1; i < D_SZ; ++i) {
        float s = 0.0f;
        for (int m = j; m < i; ++m)
            s += sL[i * D_SZ + m] * sLI[m * D_SZ + j];
        sLI[i * D_SZ + j] = -s / sL[i * D_SZ + i];
    }
    __syncthreads();

    float mm = 0.0f;
    for (int jj = 0; jj <= t; ++jj)
        mm += sLI[t * D_SZ + jj] * (means_raw[k * D_SZ + jj] * S_MEAN);
    g_m2[k * D_SZ + t] = mm;

    if (t == 0)
        g_c[k] = -0.5f * (float)D_SZ * LOG_2PI - hld + g_logw[k];

    for (int idx = t; idx < D_SZ * D_SZ; idx += D_SZ) {
        float v = sLI[idx];
        __nv_bfloat16 h = __float2bfloat16(v);
        g_Whi[(size_t)k * 4096 + idx] = h;
        g_Wlo[(size_t)k * 4096 + idx] = __float2bfloat16(v - __bfloat162float(h));
    }
}

// Main: 4 warps x 32 samples = 128 samples/block. W = hi+lo (full precision),
// x rounded once to bf16 (random error, washes out over the B-mean).
// Per nt: 4 ldmatrix.x4 shared by two A tiles; 4 independent MMA chains.
__global__ void __launch_bounds__(BLK_THREADS)
main_kernel(const float* __restrict__ x) {
    __shared__ __align__(16) unsigned char sWhi[2][D_SZ * WROW_BYTES];
    __shared__ __align__(16) unsigned char sWlo[2][D_SZ * WROW_BYTES];
    __shared__ float sm2[2][D_SZ];
    __shared__ float sred[SAMPLES_PER_BLK];

    const int tid  = threadIdx.x;
    const int warp = tid >> 5;
    const int lane = tid & 31;
    const int g    = lane >> 2;
    const int qt   = lane & 3;
    const int mbase = blockIdx.x * SAMPLES_PER_BLK + warp * 32;

    unsigned A0[16];
    unsigned A1[16];
    const float* xr0 = x + (size_t)(mbase + g) * D_SZ;
    const float* xr1 = x + (size_t)(mbase + g + 8) * D_SZ;
    const float* xr2 = x + (size_t)(mbase + g + 16) * D_SZ;
    const float* xr3 = x + (size_t)(mbase + g + 24) * D_SZ;
#pragma unroll
    for (int jt = 0; jt < 4; ++jt) {
#pragma unroll
        for (int part = 0; part < 4; ++part) {
            int jj = jt * 16 + 2 * qt + ((part & 2) ? 8 : 0);
            const float* rpa = (part & 1) ? xr1 : xr0;
            const float* rpb = (part & 1) ? xr3 : xr2;
            A0[jt * 4 + part] = pack_bf16x2(rpa[jj], rpa[jj + 1]);
            A1[jt * 4 + part] = pack_bf16x2(rpb[jj], rpb[jj + 1]);
        }
    }

    unsigned whiB0 = (unsigned)__cvta_generic_to_shared(&sWhi[0][0]);
    unsigned whiB1 = (unsigned)__cvta_generic_to_shared(&sWhi[1][0]);
    unsigned wloB0 = (unsigned)__cvta_generic_to_shared(&sWlo[0][0]);
    unsigned wloB1 = (unsigned)__cvta_generic_to_shared(&sWlo[1][0]);
    unsigned m2B0  = (unsigned)__cvta_generic_to_shared(&sm2[0][0]);
    unsigned m2B1  = (unsigned)__cvta_generic_to_shared(&sm2[1][0]);

    float mx0 = NEG_BIG, s0 = 0.0f;
    float mx1 = NEG_BIG, s1 = 0.0f;
    float mx2 = NEG_BIG, s2 = 0.0f;
    float mx3 = NEG_BIG, s3 = 0.0f;

    stage_k(tid, 0, whiB0, wloB0, m2B0);
    cp_commit();

    const unsigned rowoff = (lane & 7) * WROW_BYTES + (lane >> 3) * 16;

    for (int k = 0; k < K_SZ; ++k) {
        int buf = k & 1;
        unsigned whiB = buf ? whiB1 : whiB0;
        unsigned wloB = buf ? wloB1 : wloB0;
        if (k + 1 < K_SZ) {
            unsigned nwhi = buf ? whiB0 : whiB1;
            unsigned nwlo = buf ? wloB0 : wloB1;
            unsigned nm2  = buf ? m2B0  : m2B1;
            stage_k(tid, k + 1, nwhi, nwlo, nm2);
            cp_commit();
            cp_wait1();
        } else {
            cp_wait0();
        }
        __syncthreads();

        float ck = g_c[k];
        float mh0 = 0.0f, mh1 = 0.0f, mh2 = 0.0f, mh3 = 0.0f;
#pragma unroll
        for (int nt = 0; nt < 8; ++nt) {
            unsigned ntoff = nt * 8 * WROW_BYTES + rowoff;
            unsigned bh0, bh1, bh2, bh3, bg0, bg1, bg2, bg3;
            unsigned bl0, bl1, bl2, bl3, bm0, bm1, bm2, bm3;
            ldsm4(bh0, bh1, bh2, bh3, whiB + ntoff);
            ldsm4(bg0, bg1, bg2, bg3, whiB + ntoff + 64);
            ldsm4(bl0, bl1, bl2, bl3, wloB + ntoff);
            ldsm4(bm0, bm1, bm2, bm3, wloB + ntoff + 64);

            float m2a = sm2[buf][nt * 8 + 2 * qt];
            float m2b = sm2[buf][nt * 8 + 2 * qt + 1];

            // tile 0: hi-chain d, lo-chain e (independent)
            float d0 = 0.0f, d1 = 0.0f, d2 = 0.0f, d3 = 0.0f;
            float e0 = 0.0f, e1 = 0.0f, e2 = 0.0f, e3 = 0.0f;
            mma_bf16(d0, d1, d2, d3, A0[0],  A0[1],  A0[2],  A0[3],  bh0, bh1);
            mma_bf16(e0, e1, e2, e3, A0[0],  A0[1],  A0[2],  A0[3],  bl0, bl1);
            mma_bf16(d0, d1, d2, d3, A0[4],  A0[5],  A0[6],  A0[7],  bh2, bh3);
            mma_bf16(e0, e1, e2, e3, A0[4],  A0[5],  A0[6],  A0[7],  bl2, bl3);
            mma_bf16(d0, d1, d2, d3, A0[8],  A0[9],  A0[10], A0[11], bg0, bg1);
            mma_bf16(e0, e1, e2, e3, A0[8],  A0[9],  A0[10], A0[11], bm0, bm1);
            mma_bf16(d0, d1, d2, d3, A0[12], A0[13], A0[14], A0[15], bg2, bg3);
            mma_bf16(e0, e1, e2, e3, A0[12], A0[13], A0[14], A0[15], bm2, bm3);

            // tile 1: chains f, h
            float f0 = 0.0f, f1 = 0.0f, f2 = 0.0f, f3 = 0.0f;
            float h0 = 0.0f, h1 = 0.0f, h2 = 0.0f, h3 = 0.0f;
            mma_bf16(f0, f1, f2, f3, A1[0],  A1[1],  A1[2],  A1[3],  bh0, bh1);
            mma_bf16(h0, h1, h2, h3, A1[0],  A1[1],  A1[2],  A1[3],  bl0, bl1);
            mma_bf16(f0, f1, f2, f3, A1[4],  A1[5],  A1[6],  A1[7],  bh2, bh3);
            mma_bf16(h0, h1, h2, h3, A1[4],  A1[5],  A1[6],  A1[7],  bl2, bl3);
            mma_bf16(f0, f1, f2, f3, A1[8],  A1[9],  A1[10], A1[11], bg0, bg1);
            mma_bf16(h0, h1, h2, h3, A1[8],  A1[9],  A1[10], A1[11], bm0, bm1);
            mma_bf16(f0, f1, f2, f3, A1[12], A1[13], A1[14], A1[15], bg2, bg3);
            mma_bf16(h0, h1, h2, h3, A1[12], A1[13], A1[14], A1[15], bm2, bm3);

            float z0 = (d0 + e0) - m2a;
            float z1 = (d1 + e1) - m2b;
            float z2 = (d2 + e2) - m2a;
            float z3 = (d3 + e3) - m2b;
            mh0 = fmaf(z0, z0, fmaf(z1, z1, mh0));
            mh1 = fmaf(z2, z2, fmaf(z3, z3, mh1));

            float y0 = (f0 + h0) - m2a;
            float y1 = (f1 + h1) - m2b;
            float y2 = (f2 + h2) - m2a;
            float y3 = (f3 + h3) - m2b;
            mh2 = fmaf(y0, y0, fmaf(y1, y1, mh2));
            mh3 = fmaf(y2, y2, fmaf(y3, y3, mh3));
        }
        mh0 += __shfl_xor_sync(0xffffffffu, mh0, 1);
        mh1 += __shfl_xor_sync(0xffffffffu, mh1, 1);
        mh2 += __shfl_xor_sync(0xffffffffu, mh2, 1);
        mh3 += __shfl_xor_sync(0xffffffffu, mh3, 1);
        mh0 += __shfl_xor_sync(0xffffffffu, mh0, 2);
        mh1 += __shfl_xor_sync(0xffffffffu, mh1, 2);
        mh2 += __shfl_xor_sync(0xffffffffu, mh2, 2);
        mh3 += __shfl_xor_sync(0xffffffffu, mh3, 2);

        float comp0 = fmaf(-0.5f, mh0, ck);
        float comp1 = fmaf(-0.5f, mh1, ck);
        float comp2 = fmaf(-0.5f, mh2, ck);
        float comp3 = fmaf(-0.5f, mh3, ck);
        float nm0 = fmaxf(mx0, comp0);
        s0 = s0 * __expf(mx0 - nm0) + __expf(comp0 - nm0);
        mx0 = nm0;
        float nm1 = fmaxf(mx1, comp1);
        s1 = s1 * __expf(mx1 - nm1) + __expf(comp1 - nm1);
        mx1 = nm1;
        float nm2 = fmaxf(mx2, comp2);
        s2 = s2 * __expf(mx2 - nm2) + __expf(comp2 - nm2);
        mx2 = nm2;
        float nm3 = fmaxf(mx3, comp3);
        s3 = s3 * __expf(mx3 - nm3) + __expf(comp3 - nm3);
        mx3 = nm3;

        __syncthreads();
    }

    if (qt == 0) {
        sred[warp * 32 + g]      = mx0 + __logf(s0);
        sred[warp * 32 + 8 + g]  = mx1 + __logf(s1);
        sred[warp * 32 + 16 + g] = mx2 + __logf(s2);
        sred[warp * 32 + 24 + g] = mx3 + __logf(s3);
    }
    __syncthreads();
    for (int s = SAMPLES_PER_BLK / 2; s > 0; s >>= 1) {
        if (tid < s) sred[tid] += sred[tid + s];
        __syncthreads();
    }
    if (tid == 0) g_partial[blockIdx.x] = sred[0];
}

__global__ void final_kernel(float* __restrict__ out) {
    __shared__ float red[NBLK_MAIN];
    int t = threadIdx.x;
    red[t] = g_partial[t];
    __syncthreads();
    for (int s = NBLK_MAIN / 2; s > 0; s >>= 1) {
        if (t < s) red[t] += red[t + s];
        __syncthreads();
    }
    if (t == 0) out[0] = -red[0] / (float)B_SZ;
}

extern "C" void kernel_launch(void* const* d_in, const int* in_sizes, int n_in,
                              void* d_out, int out_size) {
    const float* x = 0;
    const float* means_raw = 0;
    const float* scale_raw = 0;
    const float* weights_raw = 0;
    for (int i = 0; i < n_in; ++i) {
        if (in_sizes[i] == B_SZ * D_SZ)        x = (const float*)d_in[i];
        if (in_sizes[i] == K_SZ * D_SZ)        means_raw = (const float*)d_in[i];
        if (in_sizes[i] == K_SZ * D_SZ * D_SZ) scale_raw = (const float*)d_in[i];
        if (in_sizes[i] == K_SZ)               weights_raw = (const float*)d_in[i];
    }

    logw_kernel<<<1, K_SZ>>>(weights_raw);
    prep_kernel<<<K_SZ, D_SZ>>>(means_raw, scale_raw);
    main_kernel<<<NBLK_MAIN, BLK_THREADS>>>(x);
    final_kernel<<<1, NBLK_MAIN>>>((float*)d_out);
}

// round 12
// speedup vs baseline: 6.8765x; 1.4890x over previous
#include <cuda_runtime.h>
#include <cuda_bf16.h>
#include <math.h>

#define B_SZ 32768
#define K_SZ 64
#define D_SZ 64

#define CHUNKS 4
#define KPC 16            // k per chunk
#define BPC 37            // blocks per chunk
#define GRID_MAIN 148     // CHUNKS * BPC = 1 block/SM, exactly 1 wave
#define THREADS_MAIN 256  // 8 warps x 16 samples
#define TILE_S 128
#define NTILES 256        // B_SZ / TILE_S

#define S_MEAN  (1.0f / 64.0f)
#define S_SCALE (1.0f / 512.0f)
#define S_W     (0.125f)
#define LOG_2PI 1.8378770664093453f
#define NEG_BIG (-3.0e38f)

// dynamic smem: W chunk 128KB | m2 4KB | c 64B  (+1KB align slack)
#define SM_M2   131072
#define SM_C    135168
#define SMEM_BYTES 137728

__device__ __nv_bfloat16 g_Wb[K_SZ * D_SZ * D_SZ];
__device__ float g_m2[K_SZ * D_SZ];
__device__ float g_c[K_SZ];
__device__ float g_logw[K_SZ];
__device__ float g_pm[CHUNKS * B_SZ];
__device__ float g_ps[CHUNKS * B_SZ];
__device__ float g_partial[128];

// ---------------- PTX helpers (braces in strings written as \173 \175) ----
__device__ __forceinline__ void cp16(unsigned dst, const void* src) {
    asm volatile("cp.async.cg.shared.global [%0], [%1], 16;"
                 :: "r"(dst), "l"(__cvta_generic_to_global(src)) : "memory");
}
__device__ __forceinline__ void cp_commit() {
    asm volatile("cp.async.commit_group;" ::: "memory");
}
__device__ __forceinline__ void cp_wait0() {
    asm volatile("cp.async.wait_group 0;" ::: "memory");
}
__device__ __forceinline__ void ldsm4(unsigned& r0, unsigned& r1,
                                      unsigned& r2, unsigned& r3, unsigned a) {
    asm volatile("ldmatrix.sync.aligned.m8n8.x4.shared.b16 \173%0,%1,%2,%3\175, [%4];"
                 : "=r"(r0), "=r"(r1), "=r"(r2), "=r"(r3) : "r"(a));
}
__device__ __forceinline__ void mma_bf16(float& c0, float& c1, float& c2, float& c3,
                                         unsigned a0, unsigned a1, unsigned a2, unsigned a3,
                                         unsigned b0, unsigned b1) {
    asm volatile("mma.sync.aligned.m16n8k16.row.col.f32.bf16.bf16.f32 "
                 "\173%0,%1,%2,%3\175, \173%4,%5,%6,%7\175, \173%8,%9\175, \173%0,%1,%2,%3\175;"
                 : "+f"(c0), "+f"(c1), "+f"(c2), "+f"(c3)
                 : "r"(a0), "r"(a1), "r"(a2), "r"(a3), "r"(b0), "r"(b1));
}
__device__ __forceinline__ unsigned pack_bf16x2(float lo, float hi) {
    __nv_bfloat162 h = __floats2bfloat162_rn(lo, hi);
    return *reinterpret_cast<unsigned*>(&h);
}

// ---------------------------------------------------------------------------
__global__ void logw_kernel(const float* __restrict__ wraw) {
    __shared__ float red[K_SZ];
    int t = threadIdx.x;
    float v = wraw[t] * S_W;
    red[t] = v;
    __syncthreads();
    for (int s = 32; s > 0; s >>= 1) {
        if (t < s) red[t] = fmaxf(red[t], red[t + s]);
        __syncthreads();
    }
    float m = red[0];
    __syncthreads();
    red[t] = __expf(v - m);
    __syncthreads();
    for (int s = 32; s > 0; s >>= 1) {
        if (t < s) red[t] += red[t + s];
        __syncthreads();
    }
    float lse = m + __logf(red[0]);
    g_logw[t] = v - lse;
}

__global__ void prep_kernel(const float* __restrict__ means_raw,
                            const float* __restrict__ scale_raw) {
    __shared__ float sL [D_SZ * D_SZ];
    __shared__ float sLI[D_SZ * D_SZ];
    __shared__ float red[D_SZ];
    int k = blockIdx.x;
    int t = threadIdx.x;
    const float* src = scale_raw + (size_t)k * D_SZ * D_SZ;

    for (int idx = t; idx < D_SZ * D_SZ; idx += D_SZ) {
        int i = idx >> 6;
        int j = idx & 63;
        float v = src[idx] * S_SCALE;
        float dv = expf(v);
        float off = (j < i) ? v : 0.0f;
        sL[idx] = (j == i) ? dv : off;
    }
    red[t] = src[t * D_SZ + t] * S_SCALE;
    __syncthreads();
    for (int s = 32; s > 0; s >>= 1) {
        if (t < s) red[t] += red[t + s];
        __syncthreads();
    }
    float hld = red[0];

    int j = t;
    for (int i = 0; i < j; ++i) sLI[i * D_SZ + j] = 0.0f;
    sLI[j * D_SZ + j] = 1.0f / sL[j * D_SZ + j];
    for (int i = j + 1; i < D_SZ; ++i) {
        float s = 0.0f;
        for (int m = j; m < i; ++m)
            s += sL[i * D_SZ + m] * sLI[m * D_SZ + j];
        sLI[i * D_SZ + j] = -s / sL[i * D_SZ + i];
    }
    __syncthreads();

    float mm = 0.0f;
    for (int jj = 0; jj <= t; ++jj)
        mm += sLI[t * D_SZ + jj] * (means_raw[k * D_SZ + jj] * S_MEAN);
    g_m2[k * D_SZ + t] = mm;

    if (t == 0)
        g_c[k] = -0.5f * (float)D_SZ * LOG_2PI - hld + g_logw[k];

    for (int idx = t; idx < D_SZ * D_SZ; idx += D_SZ)
        g_Wb[(size_t)k * 4096 + idx] = __float2bfloat16(sLI[idx]);
}

// ---------------------------------------------------------------------------
// Main: split-k persistent. Block = one k-chunk (16 k), W chunk resident in
// smem (XOR-swizzled) for the whole kernel. Loops sample tiles (128 each);
// k-loop has no barriers and no staging. Emits per-chunk partial LSE (m,s).
// ---------------------------------------------------------------------------
extern __shared__ __align__(16) char dsm[];

__global__ void __launch_bounds__(THREADS_MAIN)
main_kernel(const float* __restrict__ x) {
    const int tid  = threadIdx.x;
    const int warp = tid >> 5;
    const int lane = tid & 31;
    const int g    = lane >> 2;
    const int qt   = lane & 3;

    unsigned raw = (unsigned)__cvta_generic_to_shared(dsm);
    unsigned ab = (raw + 1023u) & ~1023u;
    char* abp = dsm + (ab - raw);

    const unsigned wa  = ab;
    const unsigned m2a = ab + SM_M2;
    const unsigned ca  = ab + SM_C;
    const float* sm2 = (const float*)(abp + SM_M2);
    const float* sc  = (const float*)(abp + SM_C);

    const int chunk = blockIdx.x & 3;
    const int jb    = blockIdx.x >> 2;     // 0..36
    const int k0    = chunk * KPC;

    // ---- stage W chunk (16k x 8KB, swizzled) + m2 + c, once ----
    for (int c = tid; c < KPC * 512; c += THREADS_MAIN) {
        int k   = c >> 9;
        int rem = c & 511;
        int row = rem >> 3;
        int cc  = rem & 7;
        unsigned dst = wa + (unsigned)(k * 8192 + row * 128 + ((cc ^ (row & 7)) * 16));
        cp16(dst, g_Wb + (size_t)(k0 + k) * 4096 + row * 64 + cc * 8);
    }
    {
        int c = tid;
        if (c < 256) cp16(m2a + (unsigned)(c * 16), g_m2 + k0 * 64 + c * 4);
        if (c < 4)   cp16(ca + (unsigned)(c * 16), g_c + k0 + c * 4);
    }
    cp_commit();
    cp_wait0();
    __syncthreads();

    // per-lane ldmatrix address pieces (swizzle col-xor is nt-invariant)
    const unsigned rbase = (unsigned)((lane & 7) * 128);
    const unsigned c0off = (unsigned)((((lane >> 3)) ^ (lane & 7)) * 16);
    const unsigned c1off = (unsigned)((((lane >> 3) + 4) ^ (lane & 7)) * 16);

    for (int t = jb; t < NTILES; t += BPC) {
        const int mb = t * TILE_S + warp * 16;
        const float* xr0 = x + (size_t)(mb + g) * D_SZ;
        const float* xr1 = x + (size_t)(mb + g + 8) * D_SZ;

        unsigned A[16];
#pragma unroll
        for (int jt = 0; jt < 4; ++jt) {
#pragma unroll
            for (int part = 0; part < 4; ++part) {
                const float* rp = (part & 1) ? xr1 : xr0;
                int jj = jt * 16 + 2 * qt + ((part & 2) ? 8 : 0);
                float2 v = *(const float2*)(rp + jj);
                A[jt * 4 + part] = pack_bf16x2(v.x, v.y);
            }
        }

        float mx0 = NEG_BIG, s0 = 0.0f;
        float mx1 = NEG_BIG, s1 = 0.0f;

        for (int kk = 0; kk < KPC; ++kk) {
            const unsigned wk = wa + (unsigned)(kk * 8192) + rbase;
            const float* m2k = sm2 + kk * 64;

            float mh0 = 0.0f, mh1 = 0.0f;
#pragma unroll
            for (int nt = 0; nt < 8; ++nt) {
                unsigned base = wk + (unsigned)(nt * 1024);
                unsigned bh0, bh1, bh2, bh3, bg0, bg1, bg2, bg3;
                ldsm4(bh0, bh1, bh2, bh3, base + c0off);
                ldsm4(bg0, bg1, bg2, bg3, base + c1off);

                float da0 = 0.0f, da1 = 0.0f, da2 = 0.0f, da3 = 0.0f;
                float db0 = 0.0f, db1 = 0.0f, db2 = 0.0f, db3 = 0.0f;
                mma_bf16(da0, da1, da2, da3, A[0],  A[1],  A[2],  A[3],  bh0, bh1);
                mma_bf16(db0, db1, db2, db3, A[8],  A[9],  A[10], A[11], bg0, bg1);
                mma_bf16(da0, da1, da2, da3, A[4],  A[5],  A[6],  A[7],  bh2, bh3);
                mma_bf16(db0, db1, db2, db3, A[12], A[13], A[14], A[15], bg2, bg3);

                float2 m2v = *(const float2*)(m2k + nt * 8 + 2 * qt);
                float z0 = (da0 + db0) - m2v.x;
                float z1 = (da1 + db1) - m2v.y;
                float z2 = (da2 + db2) - m2v.x;
                float z3 = (da3 + db3) - m2v.y;
                mh0 = fmaf(z0, z0, fmaf(z1, z1, mh0));
                mh1 = fmaf(z2, z2, fmaf(z3, z3, mh1));
            }
            mh0 += __shfl_xor_sync(0xffffffffu, mh0, 1);
            mh1 += __shfl_xor_sync(0xffffffffu, mh1, 1);
            mh0 += __shfl_xor_sync(0xffffffffu, mh0, 2);
            mh1 += __shfl_xor_sync(0xffffffffu, mh1, 2);

            float ck = sc[kk];
            float comp0 = fmaf(-0.5f, mh0, ck);
            float comp1 = fmaf(-0.5f, mh1, ck);
            float nm0 = fmaxf(mx0, comp0);
            s0 = s0 * __expf(mx0 - nm0) + __expf(comp0 - nm0);
            mx0 = nm0;
            float nm1 = fmaxf(mx1, comp1);
            s1 = s1 * __expf(mx1 - nm1) + __expf(comp1 - nm1);
            mx1 = nm1;
        }

        if (qt == 0) {
            int idx = chunk * B_SZ + mb + g;
            g_pm[idx] = mx0;
            g_ps[idx] = s0;
            g_pm[idx + 8] = mx1;
            g_ps[idx + 8] = s1;
        }
    }
}

// ---------------------------------------------------------------------------
// Combine per-chunk partial LSEs -> lp per sample -> per-block sums
// ---------------------------------------------------------------------------
__global__ void lse_reduce_kernel() {
    __shared__ float red[256];
    int t = threadIdx.x;
    int b = blockIdx.x * 256 + t;
    float m = g_pm[b];
    float s = g_ps[b];
#pragma unroll
    for (int c = 1; c < CHUNKS; ++c) {
        float mc = g_pm[c * B_SZ + b];
        float scv = g_ps[c * B_SZ + b];
        float nm = fmaxf(m, mc);
        s = s * __expf(m - nm) + scv * __expf(mc - nm);
        m = nm;
    }
    red[t] = m + __logf(s);
    __syncthreads();
    for (int s2 = 128; s2 > 0; s2 >>= 1) {
        if (t < s2) red[t] += red[t + s2];
        __syncthreads();
    }
    if (t == 0) g_partial[blockIdx.x] = red[0];
}

__global__ void final_kernel(float* __restrict__ out) {
    __shared__ float red[128];
    int t = threadIdx.x;
    red[t] = g_partial[t];
    __syncthreads();
    for (int s = 64; s > 0; s >>= 1) {
        if (t < s) red[t] += red[t + s];
        __syncthreads();
    }
    if (t == 0) out[0] = -red[0] / (float)B_SZ;
}

extern "C" void kernel_launch(void* const* d_in, const int* in_sizes, int n_in,
                              void* d_out, int out_size) {
    const float* x = 0;
    const float* means_raw = 0;
    const float* scale_raw = 0;
    const float* weights_raw = 0;
    for (int i = 0; i < n_in; ++i) {
        if (in_sizes[i] == B_SZ * D_SZ)        x = (const float*)d_in[i];
        if (in_sizes[i] == K_SZ * D_SZ)        means_raw = (const float*)d_in[i];
        if (in_sizes[i] == K_SZ * D_SZ * D_SZ) scale_raw = (const float*)d_in[i];
        if (in_sizes[i] == K_SZ)               weights_raw = (const float*)d_in[i];
    }

    cudaFuncSetAttribute(main_kernel,
                         cudaFuncAttributeMaxDynamicSharedMemorySize, SMEM_BYTES);

    logw_kernel<<<1, K_SZ>>>(weights_raw);
    prep_kernel<<<K_SZ, D_SZ>>>(means_raw, scale_raw);
    main_kernel<<<GRID_MAIN, THREADS_MAIN, SMEM_BYTES>>>(x);
    lse_reduce_kernel<<<128, 256>>>();
    final_kernel<<<1, 128>>>((float*)d_out);
}